// round 16
// baseline (speedup 1.0000x reference)
#include <cuda_runtime.h>
#include <cuda_fp16.h>
#include <math.h>
#include <stdint.h>

#define D    128
#define HH   256
#define TT   3
#define GG   64
#define EMAX 100000

#define XSU  132   // u32 stride of X/XH tile rows (264 halves = 528 B)
#define WRU1 36    // u32 stride of msg W chunk rows (64 halves + pad)
#define WRU2 20    // u32 stride of GRU W chunk rows (32 halves + pad)

// ---------------- device scratch (no allocations allowed) ----------------
__device__ __half g_linkh [EMAX * D];    // fp16 link_state (authoritative)
__device__ __half g_edgesh[EMAX * D];    // fp16 segment-sum accumulator
__device__ float  g_gs    [GG * D];
__device__ __half g_w1h   [256 * 256];
__device__ __half g_w2h   [128 * 256];
__device__ __half g_wgh   [384 * 256];

// ---------------- PTX helpers ----------------
__device__ __forceinline__ uint32_t smem_u32(const void* p) {
    uint32_t a;
    asm("{ .reg .u64 t; cvta.to.shared.u64 t, %1; cvt.u32.u64 %0, t; }" : "=r"(a) : "l"(p));
    return a;
}
__device__ __forceinline__ uint32_t packh2(float a, float b) {
    __half2 h = __floats2half2_rn(a, b);
    return *(uint32_t*)&h;
}
#define CP16(dst, src) \
    asm volatile("cp.async.ca.shared.global [%0], [%1], 16;" :: "r"(dst), "l"(src) : "memory")
#define CP16Z(dst, src, ssize) \
    asm volatile("cp.async.ca.shared.global [%0], [%1], 16, %2;" :: "r"(dst), "l"(src), "r"(ssize) : "memory")
#define CP_COMMIT() asm volatile("cp.async.commit_group;" ::: "memory")
#define CP_WAIT0()  asm volatile("cp.async.wait_group 0;" ::: "memory")
#define REDH2(addr, v) \
    asm volatile("red.global.add.noftz.f16x2 [%0], %1;" :: "l"(addr), "r"(v) : "memory")
#define LDSM4(r0, r1, r2, r3, addr) \
    asm volatile("ldmatrix.sync.aligned.m8n8.x4.shared.b16 {%0,%1,%2,%3}, [%4];" \
        : "=r"(r0), "=r"(r1), "=r"(r2), "=r"(r3) : "r"(addr))

__device__ __forceinline__ float fsigmoid(float x) {
    float e, r;
    asm("ex2.approx.f32 %0, %1;" : "=f"(e) : "f"(-1.4426950408889634f * x));
    asm("rcp.approx.f32 %0, %1;" : "=f"(r) : "f"(1.f + e));
    return r;
}
__device__ __forceinline__ float ftanh(float x) {
    float e, r;
    asm("ex2.approx.f32 %0, %1;" : "=f"(e) : "f"(-2.8853900817779268f * x));
    asm("rcp.approx.f32 %0, %1;" : "=f"(r) : "f"(1.f + e));
    return fmaf(2.f, r, -1.f);
}

__device__ __forceinline__ void mma_f16(float d[4],
                                        uint32_t a0, uint32_t a1, uint32_t a2, uint32_t a3,
                                        uint32_t b0, uint32_t b1) {
    asm volatile(
        "mma.sync.aligned.m16n8k16.row.col.f32.f16.f16.f32 "
        "{%0,%1,%2,%3}, {%4,%5,%6,%7}, {%8,%9}, {%0,%1,%2,%3};\n"
        : "+f"(d[0]), "+f"(d[1]), "+f"(d[2]), "+f"(d[3])
        : "r"(a0), "r"(a1), "r"(a2), "r"(a3), "r"(b0), "r"(b1));
}

// ---------------- utility kernels ----------------
__global__ void zero_kernel(float4* p, int n4) {
    int i = blockIdx.x * blockDim.x + threadIdx.x;
    if (i < n4) p[i] = make_float4(0.f, 0.f, 0.f, 0.f);
}
__global__ void mirror_kernel(__half* __restrict__ dsth,
                              const float4* __restrict__ src, int n4) {
    int i = blockIdx.x * blockDim.x + threadIdx.x;
    if (i < n4) {
        float4 v = src[i];
        uint2 t;
        t.x = packh2(v.x, v.y);
        t.y = packh2(v.z, v.w);
        *(uint2*)&dsth[i * 4] = t;
    }
}
__global__ void prep_all(const float* __restrict__ mW1, const float* __restrict__ mW2,
                         const float* __restrict__ gk,  const float* __restrict__ gr,
                         __half* __restrict__ w1h, __half* __restrict__ w2h,
                         __half* __restrict__ wgh) {
    int i = blockIdx.x * blockDim.x + threadIdx.x;
    if (i < 65536) {
        int k = i >> 8, n = i & 255;
        w1h[n * 256 + k] = __float2half_rn(mW1[k * 256 + n]);
    } else if (i < 98304) {
        int j = i - 65536;
        int k = j >> 7, n = j & 127;
        w2h[n * 256 + k] = __float2half_rn(mW2[k * 128 + n]);
    } else if (i < 196608) {
        int j = i - 98304;
        int n = j >> 8, k = j & 255;
        float v = (k < 128) ? gk[k * 384 + n] : gr[(k - 128) * 384 + n];
        wgh[n * 256 + k] = __float2half_rn(v);
    }
}

// =====================================================================
// message MLP: 256 threads, 64-msg tile, 2 CTAs/SM (unchanged from R15)
// =====================================================================
#define MSG_SMEM (2048 + 64 * XSU * 4 + 2 * 256 * WRU1 * 4)
__global__ __launch_bounds__(256, 2) void msg_mma_kernel(
    const __half* __restrict__ linkh,
    const int*    __restrict__ sf,
    const int*    __restrict__ ss,
    const __half* __restrict__ w1h, const float* __restrict__ b1,
    const __half* __restrict__ w2h, const float* __restrict__ b2,
    __half*       __restrict__ edgesh, int M)
{
    extern __shared__ __align__(16) char smem[];
    int*      s_sf = (int*)smem;
    int*      s_ss = (int*)(smem + 256);
    float*    s_b1 = (float*)(smem + 512);
    float*    s_b2 = (float*)(smem + 1536);
    uint32_t* Xs   = (uint32_t*)(smem + 2048);
    const uint32_t u_base = smem_u32(smem);
    const uint32_t u_X = u_base + 2048;
    const uint32_t u_W = u_base + 2048 + 64 * XSU * 4;

    const int tid  = threadIdx.x;
    const int lane = tid & 31;
    const int gid  = lane >> 2, tin = lane & 3;
    const int lrow = (lane & 7) + ((lane >> 3) & 1) * 8;
    const int lcol = (lane >> 4) * 4;
    const int wid  = tid >> 5;
    const int wm   = wid & 1;
    const int wn   = wid >> 1;
    const int m0   = blockIdx.x * 64;

    if (tid < 64) {
        int mg = m0 + tid;
        s_sf[tid] = (mg < M) ? sf[mg] : -1;
        s_ss[tid] = (mg < M) ? ss[mg] : -1;
    }
    if (tid < 128) { s_b1[tid] = b1[tid]; s_b1[128 + tid] = b1[128 + tid]; s_b2[tid] = b2[tid]; }
    __syncthreads();

    #pragma unroll
    for (int i = 0; i < 8; i++) {
        int idx = i * 256 + tid;
        int m = idx >> 5, q = idx & 31;
        int e = (q < 16) ? s_sf[m] : s_ss[m];
        uint32_t dst = u_X + (uint32_t)(m * 528 + q * 16);
        const char* src = (const char*)linkh + (size_t)max(e, 0) * 256 + (q & 15) * 16;
        int ssz = (e >= 0) ? 16 : 0;
        CP16Z(dst, src, ssz);
    }

    auto ldW1 = [&](int c, int buf) {
        #pragma unroll
        for (int i = 0; i < 8; i++) {
            int idx = i * 256 + tid;
            int row = idx >> 3, seg = idx & 7;
            uint32_t dst = u_W + (uint32_t)buf * (256 * WRU1 * 4)
                         + (uint32_t)(row * WRU1 * 4 + seg * 16);
            CP16(dst, (const char*)w1h + (row * 256 + c * 64 + seg * 8) * 2);
        }
    };
    auto ldW2 = [&](int c, int buf) {
        #pragma unroll
        for (int i = 0; i < 4; i++) {
            int idx = i * 256 + tid;
            int row = idx >> 3, seg = idx & 7;
            uint32_t dst = u_W + (uint32_t)buf * (256 * WRU1 * 4)
                         + (uint32_t)(row * WRU1 * 4 + seg * 16);
            CP16(dst, (const char*)w2h + (row * 256 + c * 64 + seg * 8) * 2);
        }
    };

    const uint32_t u_A = u_X + (uint32_t)((wm * 32 + lrow) * XSU + lcol) * 4;

    // ================= GEMM1 =================
    float acc[2][8][4];
    #pragma unroll
    for (int a = 0; a < 2; a++)
        #pragma unroll
        for (int b = 0; b < 8; b++)
            #pragma unroll
            for (int i = 0; i < 4; i++) acc[a][b][i] = 0.f;

    ldW1(0, 0); CP_COMMIT();
    for (int c = 0; c < 4; c++) {
        CP_WAIT0(); __syncthreads();
        if (c < 3) { ldW1(c + 1, (c + 1) & 1); CP_COMMIT(); }
        else       { ldW2(0, 0); CP_COMMIT(); }
        const uint32_t u_Wc = u_W + (uint32_t)(c & 1) * (256 * WRU1 * 4);
        #pragma unroll
        for (int ks = 0; ks < 4; ks++) {
            const int ku = c * 32 + ks * 8;
            const int kl = ks * 8;
            uint32_t afr[2][4];
            #pragma unroll
            for (int mt = 0; mt < 2; mt++)
                LDSM4(afr[mt][0], afr[mt][1], afr[mt][2], afr[mt][3],
                      u_A + (uint32_t)(mt * 16 * XSU + ku) * 4);
            uint32_t bfr[8][2];
            #pragma unroll
            for (int np = 0; np < 4; np++) {
                int n0 = wn * 64 + np * 16;
                uint32_t r0, r1, r2, r3;
                LDSM4(r0, r1, r2, r3,
                      u_Wc + (uint32_t)((n0 + lrow) * WRU1 + kl + lcol) * 4);
                bfr[2 * np][0] = r0; bfr[2 * np + 1][0] = r1;
                bfr[2 * np][1] = r2; bfr[2 * np + 1][1] = r3;
            }
            #pragma unroll
            for (int nt = 0; nt < 8; nt++)
                #pragma unroll
                for (int mt = 0; mt < 2; mt++)
                    mma_f16(acc[mt][nt], afr[mt][0], afr[mt][1], afr[mt][2], afr[mt][3],
                            bfr[nt][0], bfr[nt][1]);
        }
    }
    __syncthreads();

    #pragma unroll
    for (int mt = 0; mt < 2; mt++)
        #pragma unroll
        for (int nt = 0; nt < 8; nt++) {
            int r  = wm * 32 + mt * 16 + gid;
            int cb = wn * 64 + nt * 8 + tin * 2;
            int cu = cb >> 1;
            Xs[r * XSU + cu]       = packh2(fmaxf(acc[mt][nt][0] + s_b1[cb], 0.f),
                                            fmaxf(acc[mt][nt][1] + s_b1[cb + 1], 0.f));
            Xs[(r + 8) * XSU + cu] = packh2(fmaxf(acc[mt][nt][2] + s_b1[cb], 0.f),
                                            fmaxf(acc[mt][nt][3] + s_b1[cb + 1], 0.f));
        }
    __syncthreads();

    // ================= GEMM2 =================
    float ac2[2][4][4];
    #pragma unroll
    for (int a = 0; a < 2; a++)
        #pragma unroll
        for (int b = 0; b < 4; b++)
            #pragma unroll
            for (int i = 0; i < 4; i++) ac2[a][b][i] = 0.f;

    for (int c = 0; c < 4; c++) {
        CP_WAIT0(); __syncthreads();
        if (c < 3) { ldW2(c + 1, (c + 1) & 1); CP_COMMIT(); }
        const uint32_t u_Wc = u_W + (uint32_t)(c & 1) * (256 * WRU1 * 4);
        #pragma unroll
        for (int ks = 0; ks < 4; ks++) {
            const int ku = c * 32 + ks * 8;
            const int kl = ks * 8;
            uint32_t afr[2][4];
            #pragma unroll
            for (int mt = 0; mt < 2; mt++)
                LDSM4(afr[mt][0], afr[mt][1], afr[mt][2], afr[mt][3],
                      u_A + (uint32_t)(mt * 16 * XSU + ku) * 4);
            uint32_t bfr[4][2];
            #pragma unroll
            for (int np = 0; np < 2; np++) {
                int n0 = wn * 32 + np * 16;
                uint32_t r0, r1, r2, r3;
                LDSM4(r0, r1, r2, r3,
                      u_Wc + (uint32_t)((n0 + lrow) * WRU1 + kl + lcol) * 4);
                bfr[2 * np][0] = r0; bfr[2 * np + 1][0] = r1;
                bfr[2 * np][1] = r2; bfr[2 * np + 1][1] = r3;
            }
            #pragma unroll
            for (int nt = 0; nt < 4; nt++)
                #pragma unroll
                for (int mt = 0; mt < 2; mt++)
                    mma_f16(ac2[mt][nt], afr[mt][0], afr[mt][1], afr[mt][2], afr[mt][3],
                            bfr[nt][0], bfr[nt][1]);
        }
    }

    #pragma unroll
    for (int mt = 0; mt < 2; mt++)
        #pragma unroll
        for (int nt = 0; nt < 4; nt++) {
            int r  = wm * 32 + mt * 16 + gid;
            int cb = wn * 32 + nt * 8 + tin * 2;
            int e0 = s_ss[r], e1 = s_ss[r + 8];
            if (e0 >= 0) {
                uint32_t v = packh2(fmaxf(ac2[mt][nt][0] + s_b2[cb], 0.f),
                                    fmaxf(ac2[mt][nt][1] + s_b2[cb + 1], 0.f));
                REDH2(&edgesh[e0 * D + cb], v);
            }
            if (e1 >= 0) {
                uint32_t v = packh2(fmaxf(ac2[mt][nt][2] + s_b2[cb], 0.f),
                                    fmaxf(ac2[mt][nt][3] + s_b2[cb + 1], 0.f));
                REDH2(&edgesh[e1 * D + cb], v);
            }
        }
}

// =====================================================================
// GRU: 256 threads, 64-row tile, 2 CTAs/SM, TWO passes with fp16 z/r
// spill to smem (same-thread, no sync); epilogue zeroes consumed edges
// smem: biases 2048 | XH 64x528 | ZR 64x528 | W 2x256x80 = 110592
// =====================================================================
#define GRU_SMEM (2048 + 64 * XSU * 4 + 64 * XSU * 4 + 2 * 256 * WRU2 * 4)
__global__ __launch_bounds__(256, 2) void gru_mma_kernel(
    __half*       __restrict__ xh,          // fp16 edges, zeroed after use
    __half*       __restrict__ linkh,
    const __half* __restrict__ wgh,
    const float*  __restrict__ gbias,
    int E)
{
    extern __shared__ __align__(16) char smem[];
    float*    s_bz  = (float*)smem;
    float*    s_br  = (float*)(smem + 512);
    float*    s_bah = (float*)(smem + 1024);
    float*    s_bbh = (float*)(smem + 1536);
    char*     XHc   = smem + 2048;
    uint32_t* ZRu   = (uint32_t*)(smem + 2048 + 64 * XSU * 4);
    const uint32_t u_base = smem_u32(smem);
    const uint32_t u_X = u_base + 2048;
    const uint32_t u_W = u_base + 2048 + 2 * 64 * XSU * 4;

    const int tid  = threadIdx.x;
    const int lane = tid & 31;
    const int gid  = lane >> 2, tin = lane & 3;
    const int lrow = (lane & 7) + ((lane >> 3) & 1) * 8;
    const int lcol = (lane >> 4) * 4;
    const int wid  = tid >> 5;
    const int wm   = wid & 1;       // 32-row half
    const int wn   = wid >> 1;      // 0..3 (32-col group)
    const int e0   = blockIdx.x * 64;

    if (tid < 128) {
        s_bz[tid]  = gbias[tid]       + gbias[384 + tid];
        s_br[tid]  = gbias[128 + tid] + gbias[512 + tid];
        s_bah[tid] = gbias[256 + tid];
        s_bbh[tid] = gbias[640 + tid];
    }

    // ---- prologue: x-half + h-half via cp.async (4+4 per thread) ----
    #pragma unroll
    for (int i = 0; i < 4; i++) {
        int idx = i * 256 + tid;
        int m = idx >> 4, q = idx & 15;
        int e = e0 + m;
        uint32_t dst = u_X + (uint32_t)(m * 528 + q * 16);
        const char* src = (const char*)xh + (size_t)min(e, E - 1) * 256 + q * 16;
        int ssz = (e < E) ? 16 : 0;
        CP16Z(dst, src, ssz);
    }
    #pragma unroll
    for (int i = 0; i < 4; i++) {
        int idx = i * 256 + tid;
        int m = idx >> 4, q = idx & 15;
        int e = e0 + m;
        uint32_t dst = u_X + (uint32_t)(m * 528 + 256 + q * 16);
        const char* src = (const char*)linkh + (size_t)min(e, E - 1) * 256 + q * 16;
        int ssz = (e < E) ? 16 : 0;
        CP16Z(dst, src, ssz);
    }

    // W chunk loaders: 32-k slices
    auto ldP1 = [&](int c, int buf) {       // z|r rows 0..255: 1024 segs -> 4/thr
        #pragma unroll
        for (int i = 0; i < 4; i++) {
            int idx = i * 256 + tid;
            int row = idx >> 2, seg = idx & 3;
            uint32_t dst = u_W + (uint32_t)buf * (256 * WRU2 * 4)
                         + (uint32_t)(row * WRU2 * 4 + seg * 16);
            CP16(dst, (const char*)wgh + (row * 256 + c * 32 + seg * 8) * 2);
        }
    };
    auto ldP2 = [&](int c, int buf) {       // h rows 256..383: 512 segs -> 2/thr
        #pragma unroll
        for (int i = 0; i < 2; i++) {
            int idx = i * 256 + tid;
            int row = idx >> 2, seg = idx & 3;
            uint32_t dst = u_W + (uint32_t)buf * (256 * WRU2 * 4)
                         + (uint32_t)(row * WRU2 * 4 + seg * 16);
            CP16(dst, (const char*)wgh + ((256 + row) * 256 + c * 32 + seg * 8) * 2);
        }
    };

    const uint32_t u_A = u_X + (uint32_t)((wm * 32 + lrow) * XSU + lcol) * 4;

    // ================= pass1: z|r =================
    float acc1[2][8][4];
    #pragma unroll
    for (int a = 0; a < 2; a++)
        #pragma unroll
        for (int b = 0; b < 8; b++)
            #pragma unroll
            for (int i = 0; i < 4; i++) acc1[a][b][i] = 0.f;

    ldP1(0, 0); CP_COMMIT();
    for (int c = 0; c < 8; c++) {
        CP_WAIT0(); __syncthreads();
        if (c < 7) { ldP1(c + 1, (c + 1) & 1); CP_COMMIT(); }
        else       { ldP2(0, 0); CP_COMMIT(); }
        const uint32_t u_Wc = u_W + (uint32_t)(c & 1) * (256 * WRU2 * 4);
        #pragma unroll
        for (int ks = 0; ks < 2; ks++) {
            const int ku = c * 16 + ks * 8;
            const int kl = ks * 8;
            uint32_t afr[2][4];
            #pragma unroll
            for (int mt = 0; mt < 2; mt++)
                LDSM4(afr[mt][0], afr[mt][1], afr[mt][2], afr[mt][3],
                      u_A + (uint32_t)(mt * 16 * XSU + ku) * 4);
            #pragma unroll
            for (int jp = 0; jp < 4; jp++) {
                int n0 = (jp < 2) ? (wn * 32 + jp * 16)
                                  : (128 + wn * 32 + (jp - 2) * 16);
                uint32_t r0, r1, r2, r3;
                LDSM4(r0, r1, r2, r3,
                      u_Wc + (uint32_t)((n0 + lrow) * WRU2 + kl + lcol) * 4);
                #pragma unroll
                for (int mt = 0; mt < 2; mt++) {
                    mma_f16(acc1[mt][2 * jp],     afr[mt][0], afr[mt][1], afr[mt][2], afr[mt][3], r0, r2);
                    mma_f16(acc1[mt][2 * jp + 1], afr[mt][0], afr[mt][1], afr[mt][2], afr[mt][3], r1, r3);
                }
            }
        }
    }

    // ---- epilogue1: sigmoid(z), sigmoid(r) -> fp16 spill (same-thread) ----
    #pragma unroll
    for (int mt = 0; mt < 2; mt++)
        #pragma unroll
        for (int nt = 0; nt < 4; nt++) {
            int cb = wn * 32 + nt * 8 + tin * 2;
            int cu = cb >> 1;
            #pragma unroll
            for (int half_ = 0; half_ < 2; half_++) {
                int r = wm * 32 + mt * 16 + gid + half_ * 8;
                int i0 = half_ * 2;
                float z0 = fsigmoid(acc1[mt][nt][i0]         + s_bz[cb]);
                float z1 = fsigmoid(acc1[mt][nt][i0 + 1]     + s_bz[cb + 1]);
                float r0 = fsigmoid(acc1[mt][nt + 4][i0]     + s_br[cb]);
                float r1 = fsigmoid(acc1[mt][nt + 4][i0 + 1] + s_br[cb + 1]);
                ZRu[r * XSU + cu]      = packh2(z0, z1);
                ZRu[r * XSU + 66 + cu] = packh2(r0, r1);
            }
        }

    // ================= pass2: hA (c<4, x@Kh) / hB (c>=4, h@Rh) =================
    float accA[2][4][4], accB[2][4][4];
    #pragma unroll
    for (int a = 0; a < 2; a++)
        #pragma unroll
        for (int b = 0; b < 4; b++)
            #pragma unroll
            for (int i = 0; i < 4; i++) { accA[a][b][i] = 0.f; accB[a][b][i] = 0.f; }

    for (int c = 0; c < 8; c++) {
        CP_WAIT0(); __syncthreads();
        if (c < 7) { ldP2(c + 1, (c + 1) & 1); CP_COMMIT(); }
        const uint32_t u_Wc = u_W + (uint32_t)(c & 1) * (256 * WRU2 * 4);
        #pragma unroll
        for (int ks = 0; ks < 2; ks++) {
            const int ku = c * 16 + ks * 8;
            const int kl = ks * 8;
            uint32_t afr[2][4];
            #pragma unroll
            for (int mt = 0; mt < 2; mt++)
                LDSM4(afr[mt][0], afr[mt][1], afr[mt][2], afr[mt][3],
                      u_A + (uint32_t)(mt * 16 * XSU + ku) * 4);
            #pragma unroll
            for (int np = 0; np < 2; np++) {
                int n0 = wn * 32 + np * 16;
                uint32_t r0, r1, r2, r3;
                LDSM4(r0, r1, r2, r3,
                      u_Wc + (uint32_t)((n0 + lrow) * WRU2 + kl + lcol) * 4);
                if (c < 4) {
                    #pragma unroll
                    for (int mt = 0; mt < 2; mt++) {
                        mma_f16(accA[mt][2 * np],     afr[mt][0], afr[mt][1], afr[mt][2], afr[mt][3], r0, r2);
                        mma_f16(accA[mt][2 * np + 1], afr[mt][0], afr[mt][1], afr[mt][2], afr[mt][3], r1, r3);
                    }
                } else {
                    #pragma unroll
                    for (int mt = 0; mt < 2; mt++) {
                        mma_f16(accB[mt][2 * np],     afr[mt][0], afr[mt][1], afr[mt][2], afr[mt][3], r0, r2);
                        mma_f16(accB[mt][2 * np + 1], afr[mt][0], afr[mt][1], afr[mt][2], afr[mt][3], r1, r3);
                    }
                }
            }
        }
    }

    // ---- gate epilogue: z/r from spill, ho from XH; write linkh; zero edges ----
    #pragma unroll
    for (int mt = 0; mt < 2; mt++)
        #pragma unroll
        for (int nt = 0; nt < 4; nt++) {
            int cb = wn * 32 + nt * 8 + tin * 2;
            int cu = cb >> 1;
            #pragma unroll
            for (int half_ = 0; half_ < 2; half_++) {
                int r = wm * 32 + mt * 16 + gid + half_ * 8;
                int e = e0 + r;
                if (e < E) {
                    int i0 = half_ * 2;
                    float2 zz = __half22float2(*(__half2*)&ZRu[r * XSU + cu]);
                    float2 rr = __half22float2(*(__half2*)&ZRu[r * XSU + 66 + cu]);
                    float2 ho = __half22float2(*(__half2*)(XHc + r * 528 + 256 + cb * 2));
                    float h0 = ftanh(accA[mt][nt][i0]     + s_bah[cb]     + rr.x * (accB[mt][nt][i0]     + s_bbh[cb]));
                    float h1 = ftanh(accA[mt][nt][i0 + 1] + s_bah[cb + 1] + rr.y * (accB[mt][nt][i0 + 1] + s_bbh[cb + 1]));
                    float o0 = zz.x * ho.x + (1.f - zz.x) * h0;
                    float o1 = zz.y * ho.y + (1.f - zz.y) * h1;
                    *(uint32_t*)&linkh[e * D + cb] = packh2(o0, o1);
                    *(uint32_t*)&xh[e * D + cb] = 0u;      // re-zero edges for next iter
                }
            }
        }
}

// ---------------- graph segment-sum from fp16 link (sorted ids) ----------------
#define GSROWS 256
__global__ __launch_bounds__(128) void graph_sum_kernel(
    const __half* __restrict__ linkh, const int* __restrict__ gid,
    float* __restrict__ gs, int E)
{
    int tid = threadIdx.x;
    int r0 = blockIdx.x * GSROWS;
    if (r0 >= E) return;
    int r1 = min(r0 + GSROWS, E);
    float acc = 0.f;
    int cur = gid[r0];
    for (int r = r0; r < r1; r++) {
        int g = gid[r];
        if (g != cur) {
            atomicAdd(&gs[cur * D + tid], acc);
            acc = 0.f;
            cur = g;
        }
        acc += __half2float(linkh[r * D + tid]);
    }
    atomicAdd(&gs[cur * D + tid], acc);
}

// ---------------- readout MLP ----------------
__global__ __launch_bounds__(256) void readout_kernel(
    const float* __restrict__ gs,
    const float* __restrict__ rW1, const float* __restrict__ rb1,
    const float* __restrict__ rW2, const float* __restrict__ rb2,
    const float* __restrict__ rW3, const float* __restrict__ rb3,
    float* __restrict__ out)
{
    __shared__ float s_in[D];
    __shared__ float s_r1[HH];
    __shared__ float s_r2[HH];
    const int g = blockIdx.x;
    const int t = threadIdx.x;

    if (t < D) s_in[t] = gs[g * D + t];
    __syncthreads();

    float a = rb1[t];
    #pragma unroll 4
    for (int k = 0; k < D; k++) a = fmaf(s_in[k], rW1[k * HH + t], a);
    s_r1[t] = fmaxf(a, 0.f);
    __syncthreads();

    float b = rb2[t];
    #pragma unroll 4
    for (int k = 0; k < HH; k++) b = fmaf(s_r1[k], rW2[k * HH + t], b);
    s_r2[t] = fmaxf(b, 0.f) * rW3[t];
    __syncthreads();

    for (int s = 128; s > 0; s >>= 1) {
        if (t < s) s_r2[t] += s_r2[t + s];
        __syncthreads();
    }
    if (t == 0) out[g] = s_r2[0] + rb3[0];
}

// ---------------- launch ----------------
extern "C" void kernel_launch(void* const* d_in, const int* in_sizes, int n_in,
                              void* d_out, int out_size)
{
    const float* link0 = (const float*)d_in[0];
    const int*   sf    = (const int*)  d_in[1];
    const int*   ss    = (const int*)  d_in[2];
    const int*   gid   = (const int*)  d_in[3];
    const float* mW1 = (const float*)d_in[5];
    const float* mb1 = (const float*)d_in[6];
    const float* mW2 = (const float*)d_in[7];
    const float* mb2 = (const float*)d_in[8];
    const float* gk  = (const float*)d_in[9];
    const float* gr  = (const float*)d_in[10];
    const float* gb  = (const float*)d_in[11];
    const float* rW1 = (const float*)d_in[12];
    const float* rb1 = (const float*)d_in[13];
    const float* rW2 = (const float*)d_in[14];
    const float* rb2 = (const float*)d_in[15];
    const float* rW3 = (const float*)d_in[16];
    const float* rb3 = (const float*)d_in[17];
    float* out = (float*)d_out;

    const int M = in_sizes[1];
    const int E = in_sizes[3] <= EMAX ? in_sizes[3] : EMAX;

    float *gs;
    __half *linkh, *edgesh, *w1h, *w2h, *wgh;
    cudaGetSymbolAddress((void**)&linkh,  g_linkh);
    cudaGetSymbolAddress((void**)&edgesh, g_edgesh);
    cudaGetSymbolAddress((void**)&gs,     g_gs);
    cudaGetSymbolAddress((void**)&w1h,    g_w1h);
    cudaGetSymbolAddress((void**)&w2h,    g_w2h);
    cudaGetSymbolAddress((void**)&wgh,    g_wgh);

    cudaFuncSetAttribute(msg_mma_kernel, cudaFuncAttributeMaxDynamicSharedMemorySize, MSG_SMEM);
    cudaFuncSetAttribute(gru_mma_kernel, cudaFuncAttributeMaxDynamicSharedMemorySize, GRU_SMEM);

    const int n4 = E * (D / 4);
    const int nh4 = E * D * 2 / 16;
    mirror_kernel<<<(n4 + 255) / 256, 256>>>(linkh, (const float4*)link0, n4);
    prep_all<<<768, 256>>>(mW1, mW2, gk, gr, w1h, w2h, wgh);
    zero_kernel<<<(nh4 + 255) / 256, 256>>>((float4*)edgesh, nh4);  // GRU re-zeroes each iter

    const int mblocks = (M + 63) / 64;
    const int gblocks = (E + 63) / 64;
    for (int t = 0; t < TT; t++) {
        msg_mma_kernel<<<mblocks, 256, MSG_SMEM>>>(linkh, sf, ss, w1h, mb1, w2h, mb2, edgesh, M);
        gru_mma_kernel<<<gblocks, 256, GRU_SMEM>>>(edgesh, linkh, wgh, gb, E);
    }

    const int gs4 = GG * D / 4;
    zero_kernel<<<(gs4 + 255) / 256, 256>>>((float4*)gs, gs4);
    graph_sum_kernel<<<(E + GSROWS - 1) / GSROWS, 128>>>(linkh, gid, gs, E);
    readout_kernel<<<GG, 256>>>(gs, rW1, rb1, rW2, rb2, rW3, rb3, out);
}

// round 17
// speedup vs baseline: 1.1230x; 1.1230x over previous
#include <cuda_runtime.h>
#include <cuda_fp16.h>
#include <math.h>
#include <stdint.h>

#define D    128
#define HH   256
#define TT   3
#define GG   64
#define EMAX 100000

#define XSU  132   // u32 stride of X/XH tile rows (264 halves = 528 B)
#define WRU  36    // u32 stride of W chunk rows (64 halves + pad)

// ---------------- device scratch (no allocations allowed) ----------------
__device__ __half g_linkh [EMAX * D];    // fp16 link_state (authoritative)
__device__ __half g_edgesh[EMAX * D];    // fp16 segment-sum accumulator
__device__ float  g_gs    [GG * D];
__device__ __half g_w1h   [256 * 256];
__device__ __half g_w2h   [128 * 256];
__device__ __half g_wgh   [384 * 256];

// ---------------- PTX helpers ----------------
__device__ __forceinline__ uint32_t smem_u32(const void* p) {
    uint32_t a;
    asm("{ .reg .u64 t; cvta.to.shared.u64 t, %1; cvt.u32.u64 %0, t; }" : "=r"(a) : "l"(p));
    return a;
}
__device__ __forceinline__ uint32_t packh2(float a, float b) {
    __half2 h = __floats2half2_rn(a, b);
    return *(uint32_t*)&h;
}
#define CP16(dst, src) \
    asm volatile("cp.async.ca.shared.global [%0], [%1], 16;" :: "r"(dst), "l"(src) : "memory")
#define CP16Z(dst, src, ssize) \
    asm volatile("cp.async.ca.shared.global [%0], [%1], 16, %2;" :: "r"(dst), "l"(src), "r"(ssize) : "memory")
#define CP_COMMIT() asm volatile("cp.async.commit_group;" ::: "memory")
#define CP_WAIT0()  asm volatile("cp.async.wait_group 0;" ::: "memory")
#define REDH2(addr, v) \
    asm volatile("red.global.add.noftz.f16x2 [%0], %1;" :: "l"(addr), "r"(v) : "memory")
#define LDSM4(r0, r1, r2, r3, addr) \
    asm volatile("ldmatrix.sync.aligned.m8n8.x4.shared.b16 {%0,%1,%2,%3}, [%4];" \
        : "=r"(r0), "=r"(r1), "=r"(r2), "=r"(r3) : "r"(addr))

__device__ __forceinline__ float fsigmoid(float x) {
    float e, r;
    asm("ex2.approx.f32 %0, %1;" : "=f"(e) : "f"(-1.4426950408889634f * x));
    asm("rcp.approx.f32 %0, %1;" : "=f"(r) : "f"(1.f + e));
    return r;
}
__device__ __forceinline__ float ftanh(float x) {
    float e, r;
    asm("ex2.approx.f32 %0, %1;" : "=f"(e) : "f"(-2.8853900817779268f * x));
    asm("rcp.approx.f32 %0, %1;" : "=f"(r) : "f"(1.f + e));
    return fmaf(2.f, r, -1.f);
}

__device__ __forceinline__ void mma_f16(float d[4],
                                        uint32_t a0, uint32_t a1, uint32_t a2, uint32_t a3,
                                        uint32_t b0, uint32_t b1) {
    asm volatile(
        "mma.sync.aligned.m16n8k16.row.col.f32.f16.f16.f32 "
        "{%0,%1,%2,%3}, {%4,%5,%6,%7}, {%8,%9}, {%0,%1,%2,%3};\n"
        : "+f"(d[0]), "+f"(d[1]), "+f"(d[2]), "+f"(d[3])
        : "r"(a0), "r"(a1), "r"(a2), "r"(a3), "r"(b0), "r"(b1));
}

// ---------------- utility kernels ----------------
__global__ void zero_kernel(float4* p, int n4) {
    int i = blockIdx.x * blockDim.x + threadIdx.x;
    if (i < n4) p[i] = make_float4(0.f, 0.f, 0.f, 0.f);
}
__global__ void mirror_kernel(__half* __restrict__ dsth,
                              const float4* __restrict__ src, int n4) {
    int i = blockIdx.x * blockDim.x + threadIdx.x;
    if (i < n4) {
        float4 v = src[i];
        uint2 t;
        t.x = packh2(v.x, v.y);
        t.y = packh2(v.z, v.w);
        *(uint2*)&dsth[i * 4] = t;
    }
}
__global__ void prep_all(const float* __restrict__ mW1, const float* __restrict__ mW2,
                         const float* __restrict__ gk,  const float* __restrict__ gr,
                         __half* __restrict__ w1h, __half* __restrict__ w2h,
                         __half* __restrict__ wgh) {
    int i = blockIdx.x * blockDim.x + threadIdx.x;
    if (i < 65536) {
        int k = i >> 8, n = i & 255;
        w1h[n * 256 + k] = __float2half_rn(mW1[k * 256 + n]);
    } else if (i < 98304) {
        int j = i - 65536;
        int k = j >> 7, n = j & 127;
        w2h[n * 256 + k] = __float2half_rn(mW2[k * 128 + n]);
    } else if (i < 196608) {
        int j = i - 98304;
        int n = j >> 8, k = j & 255;
        float v = (k < 128) ? gk[k * 384 + n] : gr[(k - 128) * 384 + n];
        wgh[n * 256 + k] = __float2half_rn(v);
    }
}

// =====================================================================
// message MLP: 256 threads, 64-msg tile, 2 CTAs/SM (unchanged from R15)
// =====================================================================
#define MSG_SMEM (2048 + 64 * XSU * 4 + 2 * 256 * WRU * 4)
__global__ __launch_bounds__(256, 2) void msg_mma_kernel(
    const __half* __restrict__ linkh,
    const int*    __restrict__ sf,
    const int*    __restrict__ ss,
    const __half* __restrict__ w1h, const float* __restrict__ b1,
    const __half* __restrict__ w2h, const float* __restrict__ b2,
    __half*       __restrict__ edgesh, int M)
{
    extern __shared__ __align__(16) char smem[];
    int*      s_sf = (int*)smem;
    int*      s_ss = (int*)(smem + 256);
    float*    s_b1 = (float*)(smem + 512);
    float*    s_b2 = (float*)(smem + 1536);
    uint32_t* Xs   = (uint32_t*)(smem + 2048);
    const uint32_t u_base = smem_u32(smem);
    const uint32_t u_X = u_base + 2048;
    const uint32_t u_W = u_base + 2048 + 64 * XSU * 4;

    const int tid  = threadIdx.x;
    const int lane = tid & 31;
    const int gid  = lane >> 2, tin = lane & 3;
    const int lrow = (lane & 7) + ((lane >> 3) & 1) * 8;
    const int lcol = (lane >> 4) * 4;
    const int wid  = tid >> 5;
    const int wm   = wid & 1;
    const int wn   = wid >> 1;
    const int m0   = blockIdx.x * 64;

    if (tid < 64) {
        int mg = m0 + tid;
        s_sf[tid] = (mg < M) ? sf[mg] : -1;
        s_ss[tid] = (mg < M) ? ss[mg] : -1;
    }
    if (tid < 128) { s_b1[tid] = b1[tid]; s_b1[128 + tid] = b1[128 + tid]; s_b2[tid] = b2[tid]; }
    __syncthreads();

    #pragma unroll
    for (int i = 0; i < 8; i++) {
        int idx = i * 256 + tid;
        int m = idx >> 5, q = idx & 31;
        int e = (q < 16) ? s_sf[m] : s_ss[m];
        uint32_t dst = u_X + (uint32_t)(m * 528 + q * 16);
        const char* src = (const char*)linkh + (size_t)max(e, 0) * 256 + (q & 15) * 16;
        int ssz = (e >= 0) ? 16 : 0;
        CP16Z(dst, src, ssz);
    }

    auto ldW1 = [&](int c, int buf) {
        #pragma unroll
        for (int i = 0; i < 8; i++) {
            int idx = i * 256 + tid;
            int row = idx >> 3, seg = idx & 7;
            uint32_t dst = u_W + (uint32_t)buf * (256 * WRU * 4)
                         + (uint32_t)(row * WRU * 4 + seg * 16);
            CP16(dst, (const char*)w1h + (row * 256 + c * 64 + seg * 8) * 2);
        }
    };
    auto ldW2 = [&](int c, int buf) {
        #pragma unroll
        for (int i = 0; i < 4; i++) {
            int idx = i * 256 + tid;
            int row = idx >> 3, seg = idx & 7;
            uint32_t dst = u_W + (uint32_t)buf * (256 * WRU * 4)
                         + (uint32_t)(row * WRU * 4 + seg * 16);
            CP16(dst, (const char*)w2h + (row * 256 + c * 64 + seg * 8) * 2);
        }
    };

    const uint32_t u_A = u_X + (uint32_t)((wm * 32 + lrow) * XSU + lcol) * 4;

    // ================= GEMM1 =================
    float acc[2][8][4];
    #pragma unroll
    for (int a = 0; a < 2; a++)
        #pragma unroll
        for (int b = 0; b < 8; b++)
            #pragma unroll
            for (int i = 0; i < 4; i++) acc[a][b][i] = 0.f;

    ldW1(0, 0); CP_COMMIT();
    for (int c = 0; c < 4; c++) {
        CP_WAIT0(); __syncthreads();
        if (c < 3) { ldW1(c + 1, (c + 1) & 1); CP_COMMIT(); }
        else       { ldW2(0, 0); CP_COMMIT(); }
        const uint32_t u_Wc = u_W + (uint32_t)(c & 1) * (256 * WRU * 4);
        #pragma unroll
        for (int ks = 0; ks < 4; ks++) {
            const int ku = c * 32 + ks * 8;
            const int kl = ks * 8;
            uint32_t afr[2][4];
            #pragma unroll
            for (int mt = 0; mt < 2; mt++)
                LDSM4(afr[mt][0], afr[mt][1], afr[mt][2], afr[mt][3],
                      u_A + (uint32_t)(mt * 16 * XSU + ku) * 4);
            uint32_t bfr[8][2];
            #pragma unroll
            for (int np = 0; np < 4; np++) {
                int n0 = wn * 64 + np * 16;
                uint32_t r0, r1, r2, r3;
                LDSM4(r0, r1, r2, r3,
                      u_Wc + (uint32_t)((n0 + lrow) * WRU + kl + lcol) * 4);
                bfr[2 * np][0] = r0; bfr[2 * np + 1][0] = r1;
                bfr[2 * np][1] = r2; bfr[2 * np + 1][1] = r3;
            }
            #pragma unroll
            for (int nt = 0; nt < 8; nt++)
                #pragma unroll
                for (int mt = 0; mt < 2; mt++)
                    mma_f16(acc[mt][nt], afr[mt][0], afr[mt][1], afr[mt][2], afr[mt][3],
                            bfr[nt][0], bfr[nt][1]);
        }
    }
    __syncthreads();

    #pragma unroll
    for (int mt = 0; mt < 2; mt++)
        #pragma unroll
        for (int nt = 0; nt < 8; nt++) {
            int r  = wm * 32 + mt * 16 + gid;
            int cb = wn * 64 + nt * 8 + tin * 2;
            int cu = cb >> 1;
            Xs[r * XSU + cu]       = packh2(fmaxf(acc[mt][nt][0] + s_b1[cb], 0.f),
                                            fmaxf(acc[mt][nt][1] + s_b1[cb + 1], 0.f));
            Xs[(r + 8) * XSU + cu] = packh2(fmaxf(acc[mt][nt][2] + s_b1[cb], 0.f),
                                            fmaxf(acc[mt][nt][3] + s_b1[cb + 1], 0.f));
        }
    __syncthreads();

    // ================= GEMM2 =================
    float ac2[2][4][4];
    #pragma unroll
    for (int a = 0; a < 2; a++)
        #pragma unroll
        for (int b = 0; b < 4; b++)
            #pragma unroll
            for (int i = 0; i < 4; i++) ac2[a][b][i] = 0.f;

    for (int c = 0; c < 4; c++) {
        CP_WAIT0(); __syncthreads();
        if (c < 3) { ldW2(c + 1, (c + 1) & 1); CP_COMMIT(); }
        const uint32_t u_Wc = u_W + (uint32_t)(c & 1) * (256 * WRU * 4);
        #pragma unroll
        for (int ks = 0; ks < 4; ks++) {
            const int ku = c * 32 + ks * 8;
            const int kl = ks * 8;
            uint32_t afr[2][4];
            #pragma unroll
            for (int mt = 0; mt < 2; mt++)
                LDSM4(afr[mt][0], afr[mt][1], afr[mt][2], afr[mt][3],
                      u_A + (uint32_t)(mt * 16 * XSU + ku) * 4);
            uint32_t bfr[4][2];
            #pragma unroll
            for (int np = 0; np < 2; np++) {
                int n0 = wn * 32 + np * 16;
                uint32_t r0, r1, r2, r3;
                LDSM4(r0, r1, r2, r3,
                      u_Wc + (uint32_t)((n0 + lrow) * WRU + kl + lcol) * 4);
                bfr[2 * np][0] = r0; bfr[2 * np + 1][0] = r1;
                bfr[2 * np][1] = r2; bfr[2 * np + 1][1] = r3;
            }
            #pragma unroll
            for (int nt = 0; nt < 4; nt++)
                #pragma unroll
                for (int mt = 0; mt < 2; mt++)
                    mma_f16(ac2[mt][nt], afr[mt][0], afr[mt][1], afr[mt][2], afr[mt][3],
                            bfr[nt][0], bfr[nt][1]);
        }
    }

    #pragma unroll
    for (int mt = 0; mt < 2; mt++)
        #pragma unroll
        for (int nt = 0; nt < 4; nt++) {
            int r  = wm * 32 + mt * 16 + gid;
            int cb = wn * 32 + nt * 8 + tin * 2;
            int e0 = s_ss[r], e1 = s_ss[r + 8];
            if (e0 >= 0) {
                uint32_t v = packh2(fmaxf(ac2[mt][nt][0] + s_b2[cb], 0.f),
                                    fmaxf(ac2[mt][nt][1] + s_b2[cb + 1], 0.f));
                REDH2(&edgesh[e0 * D + cb], v);
            }
            if (e1 >= 0) {
                uint32_t v = packh2(fmaxf(ac2[mt][nt][2] + s_b2[cb], 0.f),
                                    fmaxf(ac2[mt][nt][3] + s_b2[cb + 1], 0.f));
                REDH2(&edgesh[e1 * D + cb], v);
            }
        }
}

// =====================================================================
// GRU: 384 threads, 96-row tile, merged k-loop (R15 structure);
// epilogue additionally zeroes the consumed edges rows
// =====================================================================
#define GRU_SMEM (2048 + 96 * XSU * 4 + 2 * 384 * WRU * 4)
__global__ __launch_bounds__(384, 1) void gru_mma_kernel(
    __half*       __restrict__ xh,          // fp16 edges; zeroed in epilogue
    __half*       __restrict__ linkh,
    const __half* __restrict__ wgh,
    const float*  __restrict__ gbias,
    int E)
{
    extern __shared__ __align__(16) char smem[];
    float*    s_bz  = (float*)smem;
    float*    s_br  = (float*)(smem + 512);
    float*    s_bah = (float*)(smem + 1024);
    float*    s_bbh = (float*)(smem + 1536);
    char*     XHc   = smem + 2048;
    const uint32_t u_base = smem_u32(smem);
    const uint32_t u_X = u_base + 2048;
    const uint32_t u_W = u_base + 2048 + 96 * XSU * 4;

    const int tid  = threadIdx.x;
    const int lane = tid & 31;
    const int gid  = lane >> 2, tin = lane & 3;
    const int lrow = (lane & 7) + ((lane >> 3) & 1) * 8;
    const int lcol = (lane >> 4) * 4;
    const int wid  = tid >> 5;
    const int wm   = wid >> 2;
    const int wn   = wid & 3;
    const int e0   = blockIdx.x * 96;

    if (tid < 128) {
        s_bz[tid]  = gbias[tid]       + gbias[384 + tid];
        s_br[tid]  = gbias[128 + tid] + gbias[512 + tid];
        s_bah[tid] = gbias[256 + tid];
        s_bbh[tid] = gbias[640 + tid];
    }

    #pragma unroll
    for (int i = 0; i < 4; i++) {
        int idx = i * 384 + tid;
        int m = idx >> 4, q = idx & 15;
        int e = e0 + m;
        uint32_t dst = u_X + (uint32_t)(m * 528 + q * 16);
        const char* src = (const char*)xh + (size_t)min(e, E - 1) * 256 + q * 16;
        int ssz = (e < E) ? 16 : 0;
        CP16Z(dst, src, ssz);
    }
    #pragma unroll
    for (int i = 0; i < 4; i++) {
        int idx = i * 384 + tid;
        int m = idx >> 4, q = idx & 15;
        int e = e0 + m;
        uint32_t dst = u_X + (uint32_t)(m * 528 + 256 + q * 16);
        const char* src = (const char*)linkh + (size_t)min(e, E - 1) * 256 + q * 16;
        int ssz = (e < E) ? 16 : 0;
        CP16Z(dst, src, ssz);
    }

    auto ldP = [&](int c, int buf) {
        #pragma unroll
        for (int i = 0; i < 8; i++) {
            int idx = i * 384 + tid;
            int row = idx >> 3, seg = idx & 7;
            uint32_t dst = u_W + (uint32_t)buf * (384 * WRU * 4)
                         + (uint32_t)(row * WRU * 4 + seg * 16);
            CP16(dst, (const char*)wgh + (row * 256 + c * 64 + seg * 8) * 2);
        }
    };

    const uint32_t u_A = u_X + (uint32_t)((wm * 32 + lrow) * XSU + lcol) * 4;

    float acc1[2][8][4], accA[2][4][4], accB[2][4][4];
    #pragma unroll
    for (int a = 0; a < 2; a++) {
        #pragma unroll
        for (int b = 0; b < 8; b++)
            #pragma unroll
            for (int i = 0; i < 4; i++) acc1[a][b][i] = 0.f;
        #pragma unroll
        for (int b = 0; b < 4; b++)
            #pragma unroll
            for (int i = 0; i < 4; i++) { accA[a][b][i] = 0.f; accB[a][b][i] = 0.f; }
    }

    ldP(0, 0); CP_COMMIT();
    for (int c = 0; c < 4; c++) {
        CP_WAIT0(); __syncthreads();
        if (c < 3) { ldP(c + 1, (c + 1) & 1); CP_COMMIT(); }
        const uint32_t u_Wc = u_W + (uint32_t)(c & 1) * (384 * WRU * 4);
        #pragma unroll
        for (int ks = 0; ks < 4; ks++) {
            const int ku = c * 32 + ks * 8;
            const int kl = ks * 8;
            uint32_t afr[2][4];
            #pragma unroll
            for (int mt = 0; mt < 2; mt++)
                LDSM4(afr[mt][0], afr[mt][1], afr[mt][2], afr[mt][3],
                      u_A + (uint32_t)(mt * 16 * XSU + ku) * 4);
            #pragma unroll
            for (int jp = 0; jp < 4; jp++) {
                int n0 = (jp < 2) ? (wn * 32 + jp * 16)
                                  : (128 + wn * 32 + (jp - 2) * 16);
                uint32_t r0, r1, r2, r3;
                LDSM4(r0, r1, r2, r3,
                      u_Wc + (uint32_t)((n0 + lrow) * WRU + kl + lcol) * 4);
                #pragma unroll
                for (int mt = 0; mt < 2; mt++) {
                    mma_f16(acc1[mt][2 * jp],     afr[mt][0], afr[mt][1], afr[mt][2], afr[mt][3], r0, r2);
                    mma_f16(acc1[mt][2 * jp + 1], afr[mt][0], afr[mt][1], afr[mt][2], afr[mt][3], r1, r3);
                }
            }
            #pragma unroll
            for (int np = 0; np < 2; np++) {
                int n0 = 256 + wn * 32 + np * 16;
                uint32_t r0, r1, r2, r3;
                LDSM4(r0, r1, r2, r3,
                      u_Wc + (uint32_t)((n0 + lrow) * WRU + kl + lcol) * 4);
                if (c < 2) {
                    #pragma unroll
                    for (int mt = 0; mt < 2; mt++) {
                        mma_f16(accA[mt][2 * np],     afr[mt][0], afr[mt][1], afr[mt][2], afr[mt][3], r0, r2);
                        mma_f16(accA[mt][2 * np + 1], afr[mt][0], afr[mt][1], afr[mt][2], afr[mt][3], r1, r3);
                    }
                } else {
                    #pragma unroll
                    for (int mt = 0; mt < 2; mt++) {
                        mma_f16(accB[mt][2 * np],     afr[mt][0], afr[mt][1], afr[mt][2], afr[mt][3], r0, r2);
                        mma_f16(accB[mt][2 * np + 1], afr[mt][0], afr[mt][1], afr[mt][2], afr[mt][3], r1, r3);
                    }
                }
            }
        }
    }

    // ---- gate math; ho from smem; write linkh; zero consumed edges ----
    #pragma unroll
    for (int mt = 0; mt < 2; mt++)
        #pragma unroll
        for (int nt = 0; nt < 4; nt++) {
            int cb = wn * 32 + nt * 8 + tin * 2;
            #pragma unroll
            for (int half_ = 0; half_ < 2; half_++) {
                int r = wm * 32 + mt * 16 + gid + half_ * 8;
                int e = e0 + r;
                if (e < E) {
                    int i0 = half_ * 2;
                    __half2 hoh = *(__half2*)(XHc + r * 528 + 256 + cb * 2);
                    float2 ho = __half22float2(hoh);
                    float z0 = fsigmoid(acc1[mt][nt][i0]         + s_bz[cb]);
                    float z1 = fsigmoid(acc1[mt][nt][i0 + 1]     + s_bz[cb + 1]);
                    float r0 = fsigmoid(acc1[mt][nt + 4][i0]     + s_br[cb]);
                    float r1 = fsigmoid(acc1[mt][nt + 4][i0 + 1] + s_br[cb + 1]);
                    float h0 = ftanh(accA[mt][nt][i0]     + s_bah[cb]     + r0 * (accB[mt][nt][i0]     + s_bbh[cb]));
                    float h1 = ftanh(accA[mt][nt][i0 + 1] + s_bah[cb + 1] + r1 * (accB[mt][nt][i0 + 1] + s_bbh[cb + 1]));
                    float o0 = z0 * ho.x + (1.f - z0) * h0;
                    float o1 = z1 * ho.y + (1.f - z1) * h1;
                    *(uint32_t*)&linkh[e * D + cb] = packh2(o0, o1);
                    *(uint32_t*)&xh[e * D + cb] = 0u;    // re-zero edges for next iter
                }
            }
        }
}

// ---------------- graph segment-sum from fp16 link (sorted ids) ----------------
#define GSROWS 128
__global__ __launch_bounds__(128) void graph_sum_kernel(
    const __half* __restrict__ linkh, const int* __restrict__ gid,
    float* __restrict__ gs, int E)
{
    int tid = threadIdx.x;
    int r0 = blockIdx.x * GSROWS;
    if (r0 >= E) return;
    int r1 = min(r0 + GSROWS, E);
    float acc = 0.f;
    int cur = gid[r0];
    for (int r = r0; r < r1; r++) {
        int g = gid[r];
        if (g != cur) {
            atomicAdd(&gs[cur * D + tid], acc);
            acc = 0.f;
            cur = g;
        }
        acc += __half2float(linkh[r * D + tid]);
    }
    atomicAdd(&gs[cur * D + tid], acc);
}

// ---------------- readout MLP ----------------
__global__ __launch_bounds__(256) void readout_kernel(
    const float* __restrict__ gs,
    const float* __restrict__ rW1, const float* __restrict__ rb1,
    const float* __restrict__ rW2, const float* __restrict__ rb2,
    const float* __restrict__ rW3, const float* __restrict__ rb3,
    float* __restrict__ out)
{
    __shared__ float s_in[D];
    __shared__ float s_r1[HH];
    __shared__ float s_r2[HH];
    const int g = blockIdx.x;
    const int t = threadIdx.x;

    if (t < D) s_in[t] = gs[g * D + t];
    __syncthreads();

    float a = rb1[t];
    #pragma unroll 4
    for (int k = 0; k < D; k++) a = fmaf(s_in[k], rW1[k * HH + t], a);
    s_r1[t] = fmaxf(a, 0.f);
    __syncthreads();

    float b = rb2[t];
    #pragma unroll 4
    for (int k = 0; k < HH; k++) b = fmaf(s_r1[k], rW2[k * HH + t], b);
    s_r2[t] = fmaxf(b, 0.f) * rW3[t];
    __syncthreads();

    for (int s = 128; s > 0; s >>= 1) {
        if (t < s) s_r2[t] += s_r2[t + s];
        __syncthreads();
    }
    if (t == 0) out[g] = s_r2[0] + rb3[0];
}

// ---------------- launch ----------------
extern "C" void kernel_launch(void* const* d_in, const int* in_sizes, int n_in,
                              void* d_out, int out_size)
{
    const float* link0 = (const float*)d_in[0];
    const int*   sf    = (const int*)  d_in[1];
    const int*   ss    = (const int*)  d_in[2];
    const int*   gid   = (const int*)  d_in[3];
    const float* mW1 = (const float*)d_in[5];
    const float* mb1 = (const float*)d_in[6];
    const float* mW2 = (const float*)d_in[7];
    const float* mb2 = (const float*)d_in[8];
    const float* gk  = (const float*)d_in[9];
    const float* gr  = (const float*)d_in[10];
    const float* gb  = (const float*)d_in[11];
    const float* rW1 = (const float*)d_in[12];
    const float* rb1 = (const float*)d_in[13];
    const float* rW2 = (const float*)d_in[14];
    const float* rb2 = (const float*)d_in[15];
    const float* rW3 = (const float*)d_in[16];
    const float* rb3 = (const float*)d_in[17];
    float* out = (float*)d_out;

    const int M = in_sizes[1];
    const int E = in_sizes[3] <= EMAX ? in_sizes[3] : EMAX;

    float *gs;
    __half *linkh, *edgesh, *w1h, *w2h, *wgh;
    cudaGetSymbolAddress((void**)&linkh,  g_linkh);
    cudaGetSymbolAddress((void**)&edgesh, g_edgesh);
    cudaGetSymbolAddress((void**)&gs,     g_gs);
    cudaGetSymbolAddress((void**)&w1h,    g_w1h);
    cudaGetSymbolAddress((void**)&w2h,    g_w2h);
    cudaGetSymbolAddress((void**)&wgh,    g_wgh);

    cudaFuncSetAttribute(msg_mma_kernel, cudaFuncAttributeMaxDynamicSharedMemorySize, MSG_SMEM);
    cudaFuncSetAttribute(gru_mma_kernel, cudaFuncAttributeMaxDynamicSharedMemorySize, GRU_SMEM);

    const int n4 = E * (D / 4);
    const int nh4 = E * D * 2 / 16;
    mirror_kernel<<<(n4 + 255) / 256, 256>>>(linkh, (const float4*)link0, n4);
    prep_all<<<768, 256>>>(mW1, mW2, gk, gr, w1h, w2h, wgh);
    zero_kernel<<<(nh4 + 255) / 256, 256>>>((float4*)edgesh, nh4);  // GRU re-zeroes each iter

    const int mblocks = (M + 63) / 64;
    const int gblocks = (E + 95) / 96;
    for (int t = 0; t < TT; t++) {
        msg_mma_kernel<<<mblocks, 256, MSG_SMEM>>>(linkh, sf, ss, w1h, mb1, w2h, mb2, edgesh, M);
        gru_mma_kernel<<<gblocks, 384, GRU_SMEM>>>(edgesh, linkh, wgh, gb, E);
    }

    const int gs4 = GG * D / 4;
    zero_kernel<<<(gs4 + 255) / 256, 256>>>((float4*)gs, gs4);
    graph_sum_kernel<<<(E + GSROWS - 1) / GSROWS, 128>>>(linkh, gid, gs, E);
    readout_kernel<<<GG, 256>>>(gs, rW1, rb1, rW2, rb2, rW3, rb3, out);
}